// round 4
// baseline (speedup 1.0000x reference)
#include <cuda_runtime.h>
#include <cuda_bf16.h>

// PatchConsistencyLoss: structure [32,32,32,32] int32, patch 4x4x4.
// Per patch (64 voxels): entropy of non-air token distribution; mean over patches.
//
// Strategy: 1 patch per 64 threads (4 patches / 256-thread block).
//  - stage 64 tokens in shared
//  - tot(non-air) via 2 warp ballots
//  - each thread sweeps the patch with 16x LDS.128 (uniform -> broadcast):
//      c      = count of my token over all 64
//      before = count of my token at index < t   (before==0 -> I am first occurrence)
//  - first-occurrence non-air threads emit -p*log(p+1e-10), p = c/tot
//  - block-reduce -> deterministic per-block partial; single-block finalize kernel.

#define NPATCH 16384
#define PPB 4
#define NBLK (NPATCH / PPB)   // 4096

__device__ float g_partial[NBLK];

__global__ __launch_bounds__(256, 8)
void patch_entropy_kernel(const int* __restrict__ s) {
    __shared__ __align__(16) int vals[PPB][64];
    __shared__ float red[256];
    __shared__ int s_nair[PPB][2];

    const int tid = threadIdx.x;
    const int g = tid >> 6;      // patch slot in block
    const int t = tid & 63;      // voxel index in patch
    const int p = blockIdx.x * PPB + g;

    // patch coords: p = ((b*8 + pd)*8 + ph)*8 + pw
    const int b  = p >> 9;
    const int r  = p & 511;
    const int pd = r >> 6;
    const int ph = (r >> 3) & 7;
    const int pw = r & 7;

    // voxel coords within patch
    const int dz = t >> 4;
    const int dy = (t >> 2) & 3;
    const int dx = t & 3;

    const int gidx = (((b << 5) + (pd << 2) + dz) << 10)
                   + (((ph << 2) + dy) << 5)
                   + (pw << 2) + dx;

    const int v = s[gidx];
    vals[g][t] = v;

    const bool air = (v == 102) | (v == 576) | (v == 3352);

    // non-air count per patch: one ballot per half-patch warp
    unsigned bal = __ballot_sync(0xffffffffu, !air);
    if ((t & 31) == 0) s_nair[g][t >> 5] = __popc(bal);
    __syncthreads();

    const int tot = s_nair[g][0] + s_nair[g][1];

    // sweep: 16 x LDS.128, uniform index -> broadcast, conflict-free
    int c = 0;
    int before = 0;
    const int4* v4 = reinterpret_cast<const int4*>(&vals[g][0]);
    #pragma unroll
    for (int j = 0; j < 16; j++) {
        const int4 w = v4[j];
        const int e = j << 2;
        const int ex = (w.x == v);
        const int ey = (w.y == v);
        const int ez = (w.z == v);
        const int ew = (w.w == v);
        c += ex + ey + ez + ew;
        before += (ex & (e     < t))
                + (ey & (e + 1 < t))
                + (ez & (e + 2 < t))
                + (ew & (e + 3 < t));
    }

    float term = 0.0f;
    if (!air && before == 0) {
        // tot >= 1 here (v itself is non-air), matching max(tot,1)
        const float pr = (float)c / (float)tot;
        term = -pr * logf(pr + 1e-10f);
    }

    // block tree-reduce (deterministic)
    red[tid] = term;
    __syncthreads();
    #pragma unroll
    for (int off = 128; off > 0; off >>= 1) {
        if (tid < off) red[tid] += red[tid + off];
        __syncthreads();
    }
    if (tid == 0) g_partial[blockIdx.x] = red[0];
}

__global__ void finalize_kernel(float* __restrict__ out) {
    __shared__ double sd[256];
    const int tid = threadIdx.x;
    double acc = 0.0;
    #pragma unroll
    for (int i = tid; i < NBLK; i += 256) acc += (double)g_partial[i];
    sd[tid] = acc;
    __syncthreads();
    #pragma unroll
    for (int off = 128; off > 0; off >>= 1) {
        if (tid < off) sd[tid] += sd[tid + off];
        __syncthreads();
    }
    if (tid == 0) out[0] = (float)(sd[0] / (16384.0 + 1e-6));
}

extern "C" void kernel_launch(void* const* d_in, const int* in_sizes, int n_in,
                              void* d_out, int out_size) {
    const int* structure = (const int*)d_in[0];
    float* out = (float*)d_out;
    patch_entropy_kernel<<<NBLK, 256>>>(structure);
    finalize_kernel<<<1, 256>>>(out);
}

// round 5
// speedup vs baseline: 1.2878x; 1.2878x over previous
#include <cuda_runtime.h>
#include <cuda_bf16.h>

// PatchConsistencyLoss: structure [32,32,32,32] int32, patch 4x4x4 -> 16384 patches x 64 voxels.
// Per patch: entropy of non-air token histogram; mean over patches.
//
// R4 strategy: 1 warp per patch, 2 voxels per lane (va = idx t, vb = idx t+32 = +2048 in gmem).
//  - intra-set equality via __match_any_sync (1 instr) for va-set and vb-set
//  - cross-set (va<->vb) via one 8-iter LDS.128 broadcast sweep
//  - unique-token representative: va-side first occurrence; vb emits only if token absent from va
//  - warp shuffle reduce; fused final reduction via last-block-done (deterministic fixed-order sum)

#define NPATCH 16384
#define WPB 8                  // warps (=patches) per 256-thread block
#define NBLK (NPATCH / WPB)    // 2048

__device__ float g_partial[NBLK];
__device__ int   g_ctr = 0;

__global__ __launch_bounds__(256, 8)
void patch_entropy_fused(const int* __restrict__ s, float* __restrict__ out) {
    __shared__ __align__(16) int sh[WPB][64];
    __shared__ float warp_sums[WPB];
    __shared__ double sd[256];
    __shared__ int s_last;

    const int tid  = threadIdx.x;
    const int w    = tid >> 5;
    const int lane = tid & 31;
    const int p    = blockIdx.x * WPB + w;

    // p = ((b*8 + pd)*8 + ph)*8 + pw
    const int b  = p >> 9;
    const int r  = p & 511;
    const int pd = r >> 6;
    const int ph = (r >> 3) & 7;
    const int pw = r & 7;

    // voxel t (0..31): dz=t>>4, dy=(t>>2)&3, dx=t&3 ; t+32 adds 2 to dz -> +2048
    const int idx = (b << 15) + (pd << 12) + (ph << 7) + (pw << 2)
                  + ((lane >> 4) << 10) + (((lane >> 2) & 3) << 5) + (lane & 3);

    const int va = s[idx];
    const int vb = s[idx + 2048];

    const bool aa = (va == 102) | (va == 576) | (va == 3352);
    const bool ab = (vb == 102) | (vb == 576) | (vb == 3352);

    const unsigned full = 0xffffffffu;
    const unsigned ma = __match_any_sync(full, va);
    const unsigned mb = __match_any_sync(full, vb);

    const int tot = __popc(__ballot_sync(full, !aa)) + __popc(__ballot_sync(full, !ab));

    // stage patch for the cross sweep
    sh[w][lane]      = va;
    sh[w][lane + 32] = vb;
    __syncwarp();

    // cross: cab = #(vb-set == va), exist_ba = any(va-set == vb)
    int cab = 0;
    int exist_ba = 0;
    const int4* A = reinterpret_cast<const int4*>(&sh[w][0]);    // va-set
    const int4* B = reinterpret_cast<const int4*>(&sh[w][32]);   // vb-set
    #pragma unroll
    for (int j = 0; j < 8; j++) {
        const int4 x = B[j];
        cab += (x.x == va) + (x.y == va) + (x.z == va) + (x.w == va);
        const int4 y = A[j];
        exist_ba |= (y.x == vb) | (y.y == vb) | (y.z == vb) | (y.w == vb);
    }

    const unsigned lt = (1u << lane) - 1u;
    const float ftot = (float)tot;   // >=1 whenever an emit happens
    float term = 0.0f;
    if (!aa && (ma & lt) == 0) {                       // va-side representative
        const float pr = (float)(__popc(ma) + cab) / ftot;
        term -= pr * __logf(pr + 1e-10f);
    }
    if (!ab && (mb & lt) == 0 && !exist_ba) {          // vb-only token representative
        const float pr = (float)__popc(mb) / ftot;
        term -= pr * __logf(pr + 1e-10f);
    }

    // warp reduce (fixed butterfly -> deterministic)
    #pragma unroll
    for (int o = 16; o > 0; o >>= 1)
        term += __shfl_xor_sync(full, term, o);
    if (lane == 0) warp_sums[w] = term;
    __syncthreads();

    if (tid == 0) {
        float bs = 0.0f;
        #pragma unroll
        for (int i = 0; i < WPB; i++) bs += warp_sums[i];
        g_partial[blockIdx.x] = bs;
        __threadfence();
        const int old = atomicAdd(&g_ctr, 1);
        s_last = (old == NBLK - 1);
    }
    __syncthreads();

    if (s_last) {
        __threadfence();
        double acc = 0.0;
        #pragma unroll
        for (int i = tid; i < NBLK; i += 256) acc += (double)g_partial[i];
        sd[tid] = acc;
        __syncthreads();
        #pragma unroll
        for (int off = 128; off > 0; off >>= 1) {
            if (tid < off) sd[tid] += sd[tid + off];
            __syncthreads();
        }
        if (tid == 0) {
            out[0] = (float)(sd[0] / (16384.0 + 1e-6));
            g_ctr = 0;   // graph-replay safe reset
        }
    }
}

extern "C" void kernel_launch(void* const* d_in, const int* in_sizes, int n_in,
                              void* d_out, int out_size) {
    const int* structure = (const int*)d_in[0];
    float* out = (float*)d_out;
    patch_entropy_fused<<<NBLK, 256>>>(structure, out);
}